// round 4
// baseline (speedup 1.0000x reference)
#include <cuda_runtime.h>
#include <cuda_bf16.h>

#define W_IN  1024
#define H_IN  1024
#define W_OUT 512
#define H_OUT 512

// Haar DWT level 1, zero left/top pad, stride 2.
// out(h',w') <- x rows {2h'-1, 2h'}, cols {2w'-1, 2w'}.
//
// Each block handles FOUR output rows (h0..h0+3) of one (b,c) plane:
// 8 consecutive input rows (2h0-1 .. 2h0+6), all 8 LDG.128 front-batched
// per thread (MLP_p1=8). Thread q owns input quad q (cols 4q..4q+3);
// col 4q-1 comes from the neighbor lane's .w via shfl (lane 0: scalar LDG).
// Streaming loads/stores (__ldcs/__stcs); per-subband float2 stores are
// lane-contiguous (256B/warp/instruction).
__global__ void __launch_bounds__(256) dwt_haar_kernel(
    const float* __restrict__ x, float* __restrict__ out, int n_bc)
{
    const int q    = threadIdx.x;
    const int lane = q & 31;
    const int h0   = blockIdx.y << 2;        // output rows h0..h0+3
    const int bc   = blockIdx.z;
    const int cb   = q << 2;                 // input col base
    const float a  = 0.7071067811865476f;

    const float* base = x + ((size_t)bc * H_IN + (size_t)(2 * h0)) * W_IN;

    // r[i] = input row 2h0-1+i  (i=0 is the pad row when h0==0)
    float4 r[8];
    #pragma unroll
    for (int i = 1; i < 8; ++i)
        r[i] = __ldcs(reinterpret_cast<const float4*>(base + (i - 1) * W_IN + cb));
    if (h0 > 0)
        r[0] = __ldcs(reinterpret_cast<const float4*>(base - W_IN + cb));
    else
        r[0] = make_float4(0.0f, 0.0f, 0.0f, 0.0f);

    // carry: col cb-1 of each row
    float m1[8];
    #pragma unroll
    for (int i = 0; i < 8; ++i)
        m1[i] = __shfl_up_sync(0xffffffffu, r[i].w, 1);
    if (lane == 0) {
        #pragma unroll
        for (int i = 0; i < 8; ++i) m1[i] = 0.0f;
        if (cb != 0) {
            #pragma unroll
            for (int i = 1; i < 8; ++i) m1[i] = __ldg(base + (i - 1) * W_IN + cb - 1);
            if (h0 > 0) m1[0] = __ldg(base - W_IN + cb - 1);
        }
    }

    const size_t P = (size_t)n_bc * H_OUT * W_OUT;     // subband plane stride
    float* o = out + ((size_t)bc * H_OUT + h0) * W_OUT + (q << 1);

    #pragma unroll
    for (int p = 0; p < 4; ++p) {            // pair p -> output row h0+p
        float4 vt = r[2 * p],     vb = r[2 * p + 1];
        float  tm1 = m1[2 * p],   bm1 = m1[2 * p + 1];

        float h0t0 = a * (tm1 + vt.x),  h1t0 = a * (vt.x - tm1);
        float h0b0 = a * (bm1 + vb.x),  h1b0 = a * (vb.x - bm1);
        float h0t1 = a * (vt.y + vt.z), h1t1 = a * (vt.z - vt.y);
        float h0b1 = a * (vb.y + vb.z), h1b1 = a * (vb.z - vb.y);

        float* op = o + p * W_OUT;
        __stcs(reinterpret_cast<float2*>(op + 0 * P),
               make_float2(a * (h0t0 + h0b0), a * (h0t1 + h0b1)));
        __stcs(reinterpret_cast<float2*>(op + 1 * P),
               make_float2(a * (h0b0 - h0t0), a * (h0b1 - h0t1)));
        __stcs(reinterpret_cast<float2*>(op + 2 * P),
               make_float2(a * (h1t0 + h1b0), a * (h1t1 + h1b1)));
        __stcs(reinterpret_cast<float2*>(op + 3 * P),
               make_float2(a * (h1b0 - h1t0), a * (h1b1 - h1t1)));
    }
}

extern "C" void kernel_launch(void* const* d_in, const int* in_sizes, int n_in,
                              void* d_out, int out_size)
{
    const float* x = (const float*)d_in[0];   // (16,3,1024,1024) fp32
    float* out = (float*)d_out;               // [LL,LH,HL,HH] each (16,3,512,512)

    const int n_bc = in_sizes[0] / (H_IN * W_IN);   // 48

    dim3 block(256, 1, 1);
    dim3 grid(1, H_OUT / 4, n_bc);            // 4 output rows per block
    dwt_haar_kernel<<<grid, block>>>(x, out, n_bc);
}

// round 5
// speedup vs baseline: 1.0088x; 1.0088x over previous
#include <cuda_runtime.h>
#include <cuda_bf16.h>

#define W_IN  1024
#define H_IN  1024
#define W_OUT 512
#define H_OUT 512

// Haar DWT level 1, zero left/top pad, stride 2.
// out(h',w') <- x rows {2h'-1, 2h'}, cols {2w'-1, 2w'}.
//
// Block = 256 threads = 2 output rows; thread i (0..127 within its row)
// owns output cols 4i..4i+3, i.e. input cols 8i-1..8i+6 of rows 2h-1, 2h.
// Per thread: 4 front-batched LDG.128 (512B/warp each), carry col 8i-1 via
// shfl of the neighbor's second quad (lane 0: scalar LDG), and one STG.128
// per subband (512B/warp each). All traffic fully coalesced + streaming.
__global__ void __launch_bounds__(256) dwt_haar_kernel(
    const float* __restrict__ x, float* __restrict__ out, int n_bc)
{
    const int i    = threadIdx.x & 127;          // position within the row
    const int lane = threadIdx.x & 31;
    const int h    = (blockIdx.y << 1) + (threadIdx.x >> 7);   // output row
    const int bc   = blockIdx.z;
    const int cb   = i << 3;                     // input col base = 8i
    const float a  = 0.7071067811865476f;

    const float* rowb = x + ((size_t)bc * H_IN + (size_t)(2 * h)) * W_IN;

    float4 vb0 = __ldcs(reinterpret_cast<const float4*>(rowb + cb));
    float4 vb1 = __ldcs(reinterpret_cast<const float4*>(rowb + cb + 4));
    float4 vt0, vt1;
    if (h > 0) {
        const float* rowt = rowb - W_IN;         // input row 2h-1
        vt0 = __ldcs(reinterpret_cast<const float4*>(rowt + cb));
        vt1 = __ldcs(reinterpret_cast<const float4*>(rowt + cb + 4));
    } else {
        vt0 = make_float4(0.f, 0.f, 0.f, 0.f);
        vt1 = make_float4(0.f, 0.f, 0.f, 0.f);
    }

    // carry = input col 8i-1 (the previous thread's vt1.w / vb1.w)
    float tm1 = __shfl_up_sync(0xffffffffu, vt1.w, 1);
    float bm1 = __shfl_up_sync(0xffffffffu, vb1.w, 1);
    if (lane == 0) {
        tm1 = 0.0f; bm1 = 0.0f;
        if (cb != 0) {
            bm1 = __ldg(rowb + cb - 1);
            if (h > 0) tm1 = __ldg(rowb - W_IN + cb - 1);
        }
    }

    // 4 output cols; input pairs: (8i-1,8i) (8i+1,8i+2) (8i+3,8i+4) (8i+5,8i+6)
    float tl[4] = { tm1,   vt0.y, vt0.w, vt1.y };
    float tr[4] = { vt0.x, vt0.z, vt1.x, vt1.z };
    float bl[4] = { bm1,   vb0.y, vb0.w, vb1.y };
    float br[4] = { vb0.x, vb0.z, vb1.x, vb1.z };

    float ll[4], lh[4], hl[4], hh[4];
    #pragma unroll
    for (int j = 0; j < 4; ++j) {
        float h0t = a * (tl[j] + tr[j]), h1t = a * (tr[j] - tl[j]);
        float h0b = a * (bl[j] + br[j]), h1b = a * (br[j] - bl[j]);
        ll[j] = a * (h0t + h0b);
        lh[j] = a * (h0b - h0t);
        hl[j] = a * (h1t + h1b);
        hh[j] = a * (h1b - h1t);
    }

    const size_t P = (size_t)n_bc * H_OUT * W_OUT;     // subband plane stride
    float* o = out + ((size_t)bc * H_OUT + h) * W_OUT + (i << 2);

    __stcs(reinterpret_cast<float4*>(o + 0 * P), make_float4(ll[0], ll[1], ll[2], ll[3]));
    __stcs(reinterpret_cast<float4*>(o + 1 * P), make_float4(lh[0], lh[1], lh[2], lh[3]));
    __stcs(reinterpret_cast<float4*>(o + 2 * P), make_float4(hl[0], hl[1], hl[2], hl[3]));
    __stcs(reinterpret_cast<float4*>(o + 3 * P), make_float4(hh[0], hh[1], hh[2], hh[3]));
}

extern "C" void kernel_launch(void* const* d_in, const int* in_sizes, int n_in,
                              void* d_out, int out_size)
{
    const float* x = (const float*)d_in[0];   // (16,3,1024,1024) fp32
    float* out = (float*)d_out;               // [LL,LH,HL,HH] each (16,3,512,512)

    const int n_bc = in_sizes[0] / (H_IN * W_IN);   // 48

    dim3 block(256, 1, 1);                    // 2 output rows per block
    dim3 grid(1, H_OUT / 2, n_bc);
    dwt_haar_kernel<<<grid, block>>>(x, out, n_bc);
}